// round 3
// baseline (speedup 1.0000x reference)
#include <cuda_runtime.h>
#include <cstdint>
#include <cstddef>

#define DI __device__ __forceinline__

static constexpr int Mdim = 8192, Ndim = 4096, Kdim = 4096;
static constexpr int MT = 128, NT = 128, KT = 32;
static constexpr int NKT = Kdim / KT;           // 128
static constexpr int ROWP = 36;                 // padded row stride (floats): bank=(4r+c)%32
static constexpr int TILE_B = 128 * ROWP * 4;   // 18432 bytes per operand tile
static constexpr int STG = 2 * TILE_B;          // 36864 bytes (A + B)
static constexpr int NSTG = 4;
static constexpr unsigned SMEM_BYTES = NSTG * STG;  // 147456

__device__ float g_wt[(size_t)Ndim * Kdim];  // W^T [n][k], tf32-rounded
__device__ float g_a [(size_t)Mdim * Kdim];  // A,          tf32-rounded

DI uint32_t smem_u32(const void* p) {
    uint32_t a;
    asm("{ .reg .u64 t; cvta.to.shared.u64 t, %1; cvt.u32.u64 %0, t; }" : "=r"(a) : "l"(p));
    return a;
}
DI void cpa16(uint32_t dst, const void* src) {
    asm volatile("cp.async.cg.shared.global [%0], [%1], 16;" :: "r"(dst), "l"(src) : "memory");
}
DI void cpa_commit() { asm volatile("cp.async.commit_group;" ::: "memory"); }
template <int N> DI void cpa_wait() {
    asm volatile("cp.async.wait_group %0;" :: "n"(N) : "memory");
}
DI float tf32_rna(float x) {
    uint32_t u; asm("cvt.rna.tf32.f32 %0, %1;" : "=r"(u) : "f"(x));
    return __uint_as_float(u);
}
DI void mma8(float* d, const uint32_t* a, const uint32_t* b) {
    asm volatile(
        "mma.sync.aligned.m16n8k8.row.col.f32.tf32.tf32.f32 "
        "{%0,%1,%2,%3}, {%4,%5,%6,%7}, {%8,%9}, {%0,%1,%2,%3};"
        : "+f"(d[0]), "+f"(d[1]), "+f"(d[2]), "+f"(d[3])
        : "r"(a[0]), "r"(a[1]), "r"(a[2]), "r"(a[3]), "r"(b[0]), "r"(b[1]));
}

// ---------- prep 1: g_wt[n][k] = tf32( q[k][n] * s[k][n/32] ), transposed ----------
__global__ void dequant_k(const int* __restrict__ q, const float* __restrict__ s) {
    __shared__ float t[32][33];
    int n0 = blockIdx.x * 32, k0 = blockIdx.y * 32;
    int tx = threadIdx.x, ty = threadIdx.y;   // 32 x 8
    int sb = n0 >> 5;
#pragma unroll
    for (int i = 0; i < 4; i++) {
        int k = k0 + ty + i * 8;
        float w = (float)q[(size_t)k * Ndim + n0 + tx] * s[(size_t)k * (Ndim / 32) + sb];
        t[ty + i * 8][tx] = tf32_rna(w);
    }
    __syncthreads();
#pragma unroll
    for (int i = 0; i < 4; i++)
        g_wt[(size_t)(n0 + ty + i * 8) * Kdim + k0 + tx] = t[tx][ty + i * 8];
}

// ---------- prep 2: round A to tf32 ----------
__global__ void round_a_k(const float4* __restrict__ in) {
    size_t i = (size_t)blockIdx.x * blockDim.x + threadIdx.x;
    float4 v = in[i];
    v.x = tf32_rna(v.x); v.y = tf32_rna(v.y); v.z = tf32_rna(v.z); v.w = tf32_rna(v.w);
    reinterpret_cast<float4*>(g_a)[i] = v;
}

// ---------- GEMM: tf32 mma.sync, 128x128x32 CTA tile, 4-stage cp.async ----------
DI void load_tile(uint32_t sb, int tid, int m0, int n0, int jt, int s) {
    const float* A = g_a  + (size_t)m0 * Kdim + jt * KT;
    const float* B = g_wt + (size_t)n0 * Kdim + jt * KT;
    uint32_t base = sb + (uint32_t)s * STG;
#pragma unroll
    for (int i = 0; i < 8; i++) {
        int idx = tid + i * 256;                 // 0..2047
        int half = idx >> 10;                    // 0 = A, 1 = B
        int j = idx & 1023;
        int r = j >> 3, c = j & 7;               // row 0..127, 16B chunk 0..7
        uint32_t dst = base + (uint32_t)half * TILE_B + (uint32_t)(r * ROWP * 4 + c * 16);
        const float* src = (half ? B : A) + (size_t)r * Kdim + c * 4;
        cpa16(dst, src);
    }
    cpa_commit();
}

__global__ void __launch_bounds__(256, 1) gemm_k(const float* __restrict__ bias,
                                                 float* __restrict__ out) {
    extern __shared__ __align__(1024) char smem[];
    uint32_t sb = smem_u32(smem);
    int tid = threadIdx.x, wid = tid >> 5, lane = tid & 31;
    int qr = lane >> 2, qt = lane & 3;          // quad row / quad thread
    int wm = wid >> 2, wn = wid & 3;            // 2 x 4 warp grid
    int n0 = blockIdx.x * NT, m0 = blockIdx.y * MT;

    float acc[4][4][4];                         // [mi][ni][frag]
#pragma unroll
    for (int a = 0; a < 4; a++)
#pragma unroll
        for (int b = 0; b < 4; b++)
#pragma unroll
            for (int c = 0; c < 4; c++) acc[a][b][c] = 0.f;

    load_tile(sb, tid, m0, n0, 0, 0);
    load_tile(sb, tid, m0, n0, 1, 1);
    load_tile(sb, tid, m0, n0, 2, 2);

    for (int jt = 0; jt < NKT; ++jt) {
        if (jt < NKT - 2)      cpa_wait<2>();
        else if (jt == NKT - 2) cpa_wait<1>();
        else                    cpa_wait<0>();
        __syncthreads();

        int s = jt & 3;
        const uint32_t* As = (const uint32_t*)(smem + (size_t)s * STG);
        const uint32_t* Bs = (const uint32_t*)(smem + (size_t)s * STG + TILE_B);

#pragma unroll
        for (int ks = 0; ks < 4; ++ks) {
            int c0 = ks * 8 + qt;
            uint32_t af[4][4], bf[4][2];
#pragma unroll
            for (int mi = 0; mi < 4; ++mi) {
                int r = wm * 64 + mi * 16 + qr;
                af[mi][0] = As[r * ROWP + c0];
                af[mi][1] = As[(r + 8) * ROWP + c0];
                af[mi][2] = As[r * ROWP + c0 + 4];
                af[mi][3] = As[(r + 8) * ROWP + c0 + 4];
            }
#pragma unroll
            for (int ni = 0; ni < 4; ++ni) {
                int r = wn * 32 + ni * 8 + qr;
                bf[ni][0] = Bs[r * ROWP + c0];
                bf[ni][1] = Bs[r * ROWP + c0 + 4];
            }
#pragma unroll
            for (int mi = 0; mi < 4; ++mi)
#pragma unroll
                for (int ni = 0; ni < 4; ++ni)
                    mma8(acc[mi][ni], af[mi], bf[ni]);
        }
        if (jt + 3 < NKT) load_tile(sb, tid, m0, n0, jt + 3, (jt + 3) & 3);
    }

    // epilogue: each thread owns 2x2 float2 per (mi, ni)
#pragma unroll
    for (int mi = 0; mi < 4; ++mi) {
        int r0 = m0 + wm * 64 + mi * 16 + qr;
#pragma unroll
        for (int ni = 0; ni < 4; ++ni) {
            int n = n0 + wn * 32 + ni * 8 + 2 * qt;
            float b0 = bias[n], b1 = bias[n + 1];
            float2 v0 = {acc[mi][ni][0] + b0, acc[mi][ni][1] + b1};
            float2 v1 = {acc[mi][ni][2] + b0, acc[mi][ni][3] + b1};
            *reinterpret_cast<float2*>(out + (size_t)r0 * Ndim + n) = v0;
            *reinterpret_cast<float2*>(out + (size_t)(r0 + 8) * Ndim + n) = v1;
        }
    }
}

extern "C" void kernel_launch(void* const* d_in, const int* in_sizes, int n_in,
                              void* d_out, int out_size) {
    const float* inp  = (const float*)d_in[0];
    const int*   qw   = (const int*)d_in[1];
    const float* sc   = (const float*)d_in[2];
    const float* bias = (const float*)d_in[3];
    float* out = (float*)d_out;

    cudaFuncSetAttribute(gemm_k, cudaFuncAttributeMaxDynamicSharedMemorySize, SMEM_BYTES);

    dequant_k<<<dim3(Ndim / 32, Kdim / 32), dim3(32, 8)>>>(qw, sc);
    round_a_k<<<(int)((size_t)Mdim * Kdim / 4 / 256), 256>>>((const float4*)inp);
    gemm_k<<<dim3(Ndim / NT, Mdim / MT), 256, SMEM_BYTES>>>(bias, out);
}

// round 4
// speedup vs baseline: 1.0922x; 1.0922x over previous
#include <cuda_runtime.h>
#include <cstdint>
#include <cstddef>

#define DI __device__ __forceinline__

static constexpr int Mdim = 8192, Ndim = 4096, Kdim = 4096;
static constexpr int MT = 256, NT = 128, KT = 32;
static constexpr int NKT = Kdim / KT;              // 128
static constexpr int ROWP = 36;                    // padded row stride (floats)
static constexpr int TILE_A = 256 * ROWP * 4;      // 36864 B
static constexpr int TILE_B = 128 * ROWP * 4;      // 18432 B
static constexpr int STG = TILE_A + TILE_B;        // 55296 B
static constexpr int NSTG = 3;
static constexpr unsigned SMEM_BYTES = NSTG * STG; // 165888

__device__ float g_wt[(size_t)Ndim * Kdim];        // W^T [n][k], tf32-rounded

DI uint32_t smem_u32(const void* p) {
    uint32_t a;
    asm("{ .reg .u64 t; cvta.to.shared.u64 t, %1; cvt.u32.u64 %0, t; }" : "=r"(a) : "l"(p));
    return a;
}
DI void cpa16(uint32_t dst, const void* src) {
    asm volatile("cp.async.cg.shared.global [%0], [%1], 16;" :: "r"(dst), "l"(src) : "memory");
}
DI void cpa_commit() { asm volatile("cp.async.commit_group;" ::: "memory"); }
template <int N> DI void cpa_wait() {
    asm volatile("cp.async.wait_group %0;" :: "n"(N) : "memory");
}
DI float tf32_rna(float x) {
    uint32_t u; asm("cvt.rna.tf32.f32 %0, %1;" : "=r"(u) : "f"(x));
    return __uint_as_float(u);
}
DI uint32_t tf32_rna_u(float x) {
    uint32_t u; asm("cvt.rna.tf32.f32 %0, %1;" : "=r"(u) : "f"(x));
    return u;
}
DI void mma8(float* d, const uint32_t* a, const uint32_t* b) {
    asm volatile(
        "mma.sync.aligned.m16n8k8.row.col.f32.tf32.tf32.f32 "
        "{%0,%1,%2,%3}, {%4,%5,%6,%7}, {%8,%9}, {%0,%1,%2,%3};"
        : "+f"(d[0]), "+f"(d[1]), "+f"(d[2]), "+f"(d[3])
        : "r"(a[0]), "r"(a[1]), "r"(a[2]), "r"(a[3]), "r"(b[0]), "r"(b[1]));
}

// ---------- prep: g_wt[n][k] = tf32( q[k][n] * s[k][n/32] ), transposed ----------
__global__ void dequant_k(const int* __restrict__ q, const float* __restrict__ s) {
    __shared__ float t[32][33];
    int n0 = blockIdx.x * 32, k0 = blockIdx.y * 32;
    int tx = threadIdx.x, ty = threadIdx.y;   // 32 x 8
    int sb = n0 >> 5;
#pragma unroll
    for (int i = 0; i < 4; i++) {
        int k = k0 + ty + i * 8;
        float w = (float)q[(size_t)k * Ndim + n0 + tx] * s[(size_t)k * (Ndim / 32) + sb];
        t[ty + i * 8][tx] = tf32_rna(w);
    }
    __syncthreads();
#pragma unroll
    for (int i = 0; i < 4; i++)
        g_wt[(size_t)(n0 + ty + i * 8) * Kdim + k0 + tx] = t[tx][ty + i * 8];
}

// ---------- GEMM: tf32 mma.sync, 256x128x32 CTA tile, 512 threads, 3-stage ----------
DI void load_tile(uint32_t sb, const float* __restrict__ A, int tid,
                  int m0, int n0, int jt, int s) {
    const float* Ap = A    + (size_t)m0 * Kdim + jt * KT;
    const float* Bp = g_wt + (size_t)n0 * Kdim + jt * KT;
    uint32_t base = sb + (uint32_t)s * STG;
#pragma unroll
    for (int i = 0; i < 6; i++) {
        int idx = tid + i * 512;                 // 0..3071
        if (idx < 2048) {                        // A: 256 rows x 8 chunks
            int r = idx >> 3, c = idx & 7;
            cpa16(base + (uint32_t)(r * ROWP * 4 + c * 16), Ap + (size_t)r * Kdim + c * 4);
        } else {                                 // B: 128 rows x 8 chunks
            int j = idx - 2048;
            int r = j >> 3, c = j & 7;
            cpa16(base + TILE_A + (uint32_t)(r * ROWP * 4 + c * 16), Bp + (size_t)r * Kdim + c * 4);
        }
    }
    cpa_commit();
}

__global__ void __launch_bounds__(512, 1) gemm_k(const float* __restrict__ A,
                                                 const float* __restrict__ bias,
                                                 float* __restrict__ out) {
    extern __shared__ __align__(1024) char smem[];
    uint32_t sb = smem_u32(smem);
    int tid = threadIdx.x, wid = tid >> 5, lane = tid & 31;
    int qr = lane >> 2, qt = lane & 3;
    int wm = wid >> 2, wn = wid & 3;            // 4 x 4 warp grid
    int n0 = blockIdx.x * NT, m0 = blockIdx.y * MT;

    float acc[4][4][4];
#pragma unroll
    for (int a = 0; a < 4; a++)
#pragma unroll
        for (int b = 0; b < 4; b++)
#pragma unroll
            for (int c = 0; c < 4; c++) acc[a][b][c] = 0.f;

    load_tile(sb, A, tid, m0, n0, 0, 0);
    load_tile(sb, A, tid, m0, n0, 1, 1);

    for (int jt = 0; jt < NKT; ++jt) {
        if (jt + 1 < NKT) cpa_wait<1>(); else cpa_wait<0>();
        __syncthreads();

        int s = jt % 3;
        const float*    Asf = (const float*)(smem + (size_t)s * STG);
        const uint32_t* Bs  = (const uint32_t*)(smem + (size_t)s * STG + TILE_A);

#pragma unroll
        for (int ks = 0; ks < 4; ++ks) {
            int c0 = ks * 8 + qt;
            uint32_t af[4][4], bf[4][2];
#pragma unroll
            for (int mi = 0; mi < 4; ++mi) {
                int r = wm * 64 + mi * 16 + qr;
                af[mi][0] = tf32_rna_u(Asf[r * ROWP + c0]);
                af[mi][1] = tf32_rna_u(Asf[(r + 8) * ROWP + c0]);
                af[mi][2] = tf32_rna_u(Asf[r * ROWP + c0 + 4]);
                af[mi][3] = tf32_rna_u(Asf[(r + 8) * ROWP + c0 + 4]);
            }
#pragma unroll
            for (int ni = 0; ni < 4; ++ni) {
                int r = wn * 32 + ni * 8 + qr;
                bf[ni][0] = Bs[r * ROWP + c0];
                bf[ni][1] = Bs[r * ROWP + c0 + 4];
            }
#pragma unroll
            for (int mi = 0; mi < 4; ++mi)
#pragma unroll
                for (int ni = 0; ni < 4; ++ni)
                    mma8(acc[mi][ni], af[mi], bf[ni]);
        }
        if (jt + 2 < NKT) load_tile(sb, A, tid, m0, n0, jt + 2, (jt + 2) % 3);
    }

#pragma unroll
    for (int mi = 0; mi < 4; ++mi) {
        int r0 = m0 + wm * 64 + mi * 16 + qr;
#pragma unroll
        for (int ni = 0; ni < 4; ++ni) {
            int n = n0 + wn * 32 + ni * 8 + 2 * qt;
            float b0 = bias[n], b1 = bias[n + 1];
            float2 v0 = {acc[mi][ni][0] + b0, acc[mi][ni][1] + b1};
            float2 v1 = {acc[mi][ni][2] + b0, acc[mi][ni][3] + b1};
            *reinterpret_cast<float2*>(out + (size_t)r0 * Ndim + n) = v0;
            *reinterpret_cast<float2*>(out + (size_t)(r0 + 8) * Ndim + n) = v1;
        }
    }
}

extern "C" void kernel_launch(void* const* d_in, const int* in_sizes, int n_in,
                              void* d_out, int out_size) {
    const float* inp  = (const float*)d_in[0];
    const int*   qw   = (const int*)d_in[1];
    const float* sc   = (const float*)d_in[2];
    const float* bias = (const float*)d_in[3];
    float* out = (float*)d_out;

    cudaFuncSetAttribute(gemm_k, cudaFuncAttributeMaxDynamicSharedMemorySize, SMEM_BYTES);

    dequant_k<<<dim3(Ndim / 32, Kdim / 32), dim3(32, 8)>>>(qw, sc);
    gemm_k<<<dim3(Ndim / NT, Mdim / MT), 512, SMEM_BYTES>>>(inp, bias, out);
}

// round 5
// speedup vs baseline: 1.1958x; 1.0948x over previous
#include <cuda_runtime.h>
#include <cstdint>
#include <cstddef>

#define DI __device__ __forceinline__

static constexpr int Mdim = 8192, Ndim = 4096, Kdim = 4096;
static constexpr int MT = 256, NT = 128, KT = 32;
static constexpr int NKT = Kdim / KT;              // 128
static constexpr int ROWP = 40;                    // padded row stride (floats)
static constexpr int RP2 = ROWP / 2;               // stride in 8B units (20)
static constexpr int TILE_A = 256 * ROWP * 4;      // 40960 B
static constexpr int TILE_B = 128 * ROWP * 4;      // 20480 B
static constexpr int STG = TILE_A + TILE_B;        // 61440 B
static constexpr unsigned SMEM_BYTES = 3 * STG;    // 184320

// K-pair interleaved layouts: within each 8-k group, order is [k0,k4][k1,k5][k2,k6][k3,k7]
__device__ float g_wt[(size_t)Ndim * Kdim];        // W^T [n][k-interleaved], tf32-rounded
__device__ float g_a [(size_t)Mdim * Kdim];        // A   [m][k-interleaved], tf32-rounded

DI uint32_t smem_u32(const void* p) {
    uint32_t a;
    asm("{ .reg .u64 t; cvta.to.shared.u64 t, %1; cvt.u32.u64 %0, t; }" : "=r"(a) : "l"(p));
    return a;
}
DI void cpa16(uint32_t dst, const void* src) {
    asm volatile("cp.async.cg.shared.global [%0], [%1], 16;" :: "r"(dst), "l"(src) : "memory");
}
DI void cpa_commit() { asm volatile("cp.async.commit_group;" ::: "memory"); }
template <int N> DI void cpa_wait() {
    asm volatile("cp.async.wait_group %0;" :: "n"(N) : "memory");
}
DI float tf32_rna(float x) {
    uint32_t u; asm("cvt.rna.tf32.f32 %0, %1;" : "=r"(u) : "f"(x));
    return __uint_as_float(u);
}
DI void mma8(float* d, uint32_t a0, uint32_t a1, uint32_t a2, uint32_t a3,
             uint32_t b0, uint32_t b1) {
    asm volatile(
        "mma.sync.aligned.m16n8k8.row.col.f32.tf32.tf32.f32 "
        "{%0,%1,%2,%3}, {%4,%5,%6,%7}, {%8,%9}, {%0,%1,%2,%3};"
        : "+f"(d[0]), "+f"(d[1]), "+f"(d[2]), "+f"(d[3])
        : "r"(a0), "r"(a1), "r"(a2), "r"(a3), "r"(b0), "r"(b1));
}

// ---------- prep 1: g_wt[n][ik] = tf32(q[k][n]*s[k][n/32]), transposed + k-interleaved ----------
__global__ void dequant_k(const int* __restrict__ q, const float* __restrict__ s) {
    __shared__ float t[32][33];
    int n0 = blockIdx.x * 32, k0 = blockIdx.y * 32;
    int tx = threadIdx.x, ty = threadIdx.y;   // 32 x 8
    int sb = n0 >> 5;
#pragma unroll
    for (int i = 0; i < 4; i++) {
        int k = k0 + ty + i * 8;
        float w = (float)q[(size_t)k * Ndim + n0 + tx] * s[(size_t)k * (Ndim / 32) + sb];
        t[ty + i * 8][tx] = tf32_rna(w);
    }
    __syncthreads();
    // interleave within 8-k group: newpos = (tx&24) | ((tx&3)<<1) | ((tx>>2)&1)
    int itx = (tx & 24) | ((tx & 3) << 1) | ((tx >> 2) & 1);
#pragma unroll
    for (int i = 0; i < 4; i++)
        g_wt[(size_t)(n0 + ty + i * 8) * Kdim + k0 + itx] = t[tx][ty + i * 8];
}

// ---------- prep 2: round A to tf32 + k-interleave ----------
__global__ void round_a_k(const float* __restrict__ in) {
    size_t idx = (size_t)blockIdx.x * blockDim.x + threadIdx.x;  // M*K/2 threads
    size_t m = idx >> 11;                  // K/2 = 2048
    int rem = (int)(idx & 2047);
    int g = rem >> 2, p = rem & 3;
    const float* row = in + m * Kdim + g * 8;
    float2 v = { tf32_rna(row[p]), tf32_rna(row[p + 4]) };
    *reinterpret_cast<float2*>(g_a + m * Kdim + g * 8 + 2 * p) = v;
}

// ---------- GEMM: tf32 mma.sync, 256x128x32 CTA tile, 512 threads, 3-stage ----------
DI void load_tile(uint32_t sb, int tid, int m0, int n0, int jt, int s) {
    const float* Ap = g_a  + (size_t)m0 * Kdim + jt * KT;
    const float* Bp = g_wt + (size_t)n0 * Kdim + jt * KT;
    uint32_t base = sb + (uint32_t)s * STG;
#pragma unroll
    for (int i = 0; i < 6; i++) {
        int idx = tid + i * 512;                 // 0..3071
        if (idx < 2048) {                        // A: 256 rows x 8 chunks of 16B
            int r = idx >> 3, c = idx & 7;
            cpa16(base + (uint32_t)(r * ROWP * 4 + c * 16), Ap + (size_t)r * Kdim + c * 4);
        } else {                                 // B: 128 rows x 8 chunks
            int j = idx - 2048;
            int r = j >> 3, c = j & 7;
            cpa16(base + TILE_A + (uint32_t)(r * ROWP * 4 + c * 16), Bp + (size_t)r * Kdim + c * 4);
        }
    }
    cpa_commit();
}

__global__ void __launch_bounds__(512, 1) gemm_k(const float* __restrict__ bias,
                                                 float* __restrict__ out) {
    extern __shared__ __align__(1024) char smem[];
    uint32_t sb = smem_u32(smem);
    int tid = threadIdx.x, wid = tid >> 5, lane = tid & 31;
    int qr = lane >> 2, qt = lane & 3;
    int wm = wid >> 2, wn = wid & 3;            // 4 x 4 warp grid
    int n0 = blockIdx.x * NT, m0 = blockIdx.y * MT;
    int rA = wm * 64 + qr;                      // A fragment base row
    int rB = wn * 32 + qr;                      // B fragment base row

    float acc[4][4][4];
#pragma unroll
    for (int a = 0; a < 4; a++)
#pragma unroll
        for (int b = 0; b < 4; b++)
#pragma unroll
            for (int c = 0; c < 4; c++) acc[a][b][c] = 0.f;

    load_tile(sb, tid, m0, n0, 0, 0);
    load_tile(sb, tid, m0, n0, 1, 1);

    for (int jt = 0; jt < NKT; ++jt) {
        if (jt + 1 < NKT) cpa_wait<1>(); else cpa_wait<0>();
        __syncthreads();

        int s = jt % 3;
        const uint2* As2 = (const uint2*)(smem + (size_t)s * STG) + (size_t)rA * RP2;
        const uint2* Bs2 = (const uint2*)(smem + (size_t)s * STG + TILE_A) + (size_t)rB * RP2;

#pragma unroll
        for (int ks = 0; ks < 4; ++ks) {
            int co = ks * 4 + qt;               // 8B slot within row
            uint2 a0[4], a1[4], bb[4];
#pragma unroll
            for (int mi = 0; mi < 4; ++mi) {
                a0[mi] = As2[(mi * 16)     * RP2 + co];
                a1[mi] = As2[(mi * 16 + 8) * RP2 + co];
            }
#pragma unroll
            for (int ni = 0; ni < 4; ++ni)
                bb[ni] = Bs2[(ni * 8) * RP2 + co];
#pragma unroll
            for (int mi = 0; mi < 4; ++mi)
#pragma unroll
                for (int ni = 0; ni < 4; ++ni)
                    mma8(acc[mi][ni], a0[mi].x, a1[mi].x, a0[mi].y, a1[mi].y,
                         bb[ni].x, bb[ni].y);
        }
        if (jt + 2 < NKT) load_tile(sb, tid, m0, n0, jt + 2, (jt + 2) % 3);
    }

#pragma unroll
    for (int mi = 0; mi < 4; ++mi) {
        int r0 = m0 + wm * 64 + mi * 16 + qr;
#pragma unroll
        for (int ni = 0; ni < 4; ++ni) {
            int n = n0 + wn * 32 + ni * 8 + 2 * qt;
            float b0 = bias[n], b1 = bias[n + 1];
            float2 v0 = {acc[mi][ni][0] + b0, acc[mi][ni][1] + b1};
            float2 v1 = {acc[mi][ni][2] + b0, acc[mi][ni][3] + b1};
            *reinterpret_cast<float2*>(out + (size_t)r0 * Ndim + n) = v0;
            *reinterpret_cast<float2*>(out + (size_t)(r0 + 8) * Ndim + n) = v1;
        }
    }
}

extern "C" void kernel_launch(void* const* d_in, const int* in_sizes, int n_in,
                              void* d_out, int out_size) {
    const float* inp  = (const float*)d_in[0];
    const int*   qw   = (const int*)d_in[1];
    const float* sc   = (const float*)d_in[2];
    const float* bias = (const float*)d_in[3];
    float* out = (float*)d_out;

    cudaFuncSetAttribute(gemm_k, cudaFuncAttributeMaxDynamicSharedMemorySize, SMEM_BYTES);

    dequant_k<<<dim3(Ndim / 32, Kdim / 32), dim3(32, 8)>>>(qw, sc);
    round_a_k<<<(int)((size_t)Mdim * Kdim / 2 / 256), 256>>>(inp);
    gemm_k<<<dim3(Ndim / NT, Mdim / MT), 512, SMEM_BYTES>>>(bias, out);
}

// round 6
// speedup vs baseline: 1.2094x; 1.0114x over previous
#include <cuda_runtime.h>
#include <cstdint>
#include <cstddef>

#define DI __device__ __forceinline__

static constexpr int Mdim = 8192, Ndim = 4096, Kdim = 4096;
static constexpr int MT = 256, NT = 128, KT = 32;
static constexpr int NKT = Kdim / KT;              // 128
static constexpr int ROWP = 40;                    // padded row stride (floats)
static constexpr int RP2 = ROWP / 2;               // stride in 8B units (20)
static constexpr int TILE_A = 256 * ROWP * 4;      // 40960 B
static constexpr int TILE_B = 128 * ROWP * 4;      // 20480 B
static constexpr int STG = TILE_A + TILE_B;        // 61440 B
static constexpr unsigned SMEM_BYTES = 3 * STG;    // 184320

// K-pair interleaved layouts: within each 8-k group, order is [k0,k4][k1,k5][k2,k6][k3,k7]
__device__ float g_wt[(size_t)Ndim * Kdim];        // W^T [n][k-interleaved], tf32-rounded
__device__ float g_a [(size_t)Mdim * Kdim];        // A   [m][k-interleaved], tf32-rounded

DI uint32_t smem_u32(const void* p) {
    uint32_t a;
    asm("{ .reg .u64 t; cvta.to.shared.u64 t, %1; cvt.u32.u64 %0, t; }" : "=r"(a) : "l"(p));
    return a;
}
DI void cpa16(uint32_t dst, const void* src) {
    asm volatile("cp.async.cg.shared.global [%0], [%1], 16;" :: "r"(dst), "l"(src) : "memory");
}
DI void cpa_commit() { asm volatile("cp.async.commit_group;" ::: "memory"); }
template <int N> DI void cpa_wait() {
    asm volatile("cp.async.wait_group %0;" :: "n"(N) : "memory");
}
DI float tf32_rna(float x) {
    uint32_t u; asm("cvt.rna.tf32.f32 %0, %1;" : "=r"(u) : "f"(x));
    return __uint_as_float(u);
}
DI void mma8(float* d, uint32_t a0, uint32_t a1, uint32_t a2, uint32_t a3,
             uint32_t b0, uint32_t b1) {
    asm volatile(
        "mma.sync.aligned.m16n8k8.row.col.f32.tf32.tf32.f32 "
        "{%0,%1,%2,%3}, {%4,%5,%6,%7}, {%8,%9}, {%0,%1,%2,%3};"
        : "+f"(d[0]), "+f"(d[1]), "+f"(d[2]), "+f"(d[3])
        : "r"(a0), "r"(a1), "r"(a2), "r"(a3), "r"(b0), "r"(b1));
}

// ---------- prep 1: g_wt[n][ik] = tf32(q[k][n]*s[k][n/32]), transposed + k-interleaved ----------
__global__ void dequant_k(const int* __restrict__ q, const float* __restrict__ s) {
    __shared__ float t[32][33];
    int n0 = blockIdx.x * 32, k0 = blockIdx.y * 32;
    int tx = threadIdx.x, ty = threadIdx.y;   // 32 x 8
    int sb = n0 >> 5;
#pragma unroll
    for (int i = 0; i < 4; i++) {
        int k = k0 + ty + i * 8;
        float w = (float)q[(size_t)k * Ndim + n0 + tx] * s[(size_t)k * (Ndim / 32) + sb];
        t[ty + i * 8][tx] = tf32_rna(w);
    }
    __syncthreads();
    // interleave within 8-k group: newpos = (tx&24) | ((tx&3)<<1) | ((tx>>2)&1)
    int itx = (tx & 24) | ((tx & 3) << 1) | ((tx >> 2) & 1);
#pragma unroll
    for (int i = 0; i < 4; i++)
        g_wt[(size_t)(n0 + ty + i * 8) * Kdim + k0 + itx] = t[tx][ty + i * 8];
}

// ---------- prep 2: round A to tf32 + k-interleave ----------
__global__ void round_a_k(const float* __restrict__ in) {
    size_t idx = (size_t)blockIdx.x * blockDim.x + threadIdx.x;  // M*K/2 threads
    size_t m = idx >> 11;                  // K/2 = 2048
    int rem = (int)(idx & 2047);
    int g = rem >> 2, p = rem & 3;
    const float* row = in + m * Kdim + g * 8;
    float2 v = { tf32_rna(row[p]), tf32_rna(row[p + 4]) };
    *reinterpret_cast<float2*>(g_a + m * Kdim + g * 8 + 2 * p) = v;
}

// ---------- GEMM: tf32 mma.sync, 256x128x32 CTA, 256 thr, warp tile 64x64 ----------
DI void load_tile(uint32_t sb, int tid, int m0, int n0, int jt, int s) {
    const float* Ap = g_a  + (size_t)m0 * Kdim + jt * KT;
    const float* Bp = g_wt + (size_t)n0 * Kdim + jt * KT;
    uint32_t base = sb + (uint32_t)s * STG;
#pragma unroll
    for (int i = 0; i < 12; i++) {
        int idx = tid + i * 256;                 // 0..3071
        if (idx < 2048) {                        // A: 256 rows x 8 chunks of 16B
            int r = idx >> 3, c = idx & 7;
            cpa16(base + (uint32_t)(r * ROWP * 4 + c * 16), Ap + (size_t)r * Kdim + c * 4);
        } else {                                 // B: 128 rows x 8 chunks
            int j = idx - 2048;
            int r = j >> 3, c = j & 7;
            cpa16(base + TILE_A + (uint32_t)(r * ROWP * 4 + c * 16), Bp + (size_t)r * Kdim + c * 4);
        }
    }
    cpa_commit();
}

__global__ void __launch_bounds__(256, 1) gemm_k(const float* __restrict__ bias,
                                                 float* __restrict__ out) {
    extern __shared__ __align__(1024) char smem[];
    uint32_t sb = smem_u32(smem);
    int tid = threadIdx.x, wid = tid >> 5, lane = tid & 31;
    int qr = lane >> 2, qt = lane & 3;
    int wm = wid >> 1, wn = wid & 1;            // 4 x 2 warp grid, 64x64 warp tile
    int n0 = blockIdx.x * NT, m0 = blockIdx.y * MT;
    int rA = wm * 64 + qr;                      // A fragment base row
    int rB = wn * 64 + qr;                      // B fragment base row

    float acc[4][8][4];
#pragma unroll
    for (int a = 0; a < 4; a++)
#pragma unroll
        for (int b = 0; b < 8; b++)
#pragma unroll
            for (int c = 0; c < 4; c++) acc[a][b][c] = 0.f;

    load_tile(sb, tid, m0, n0, 0, 0);
    load_tile(sb, tid, m0, n0, 1, 1);

    for (int jt = 0; jt < NKT; ++jt) {
        if (jt + 1 < NKT) cpa_wait<1>(); else cpa_wait<0>();
        __syncthreads();

        int s = jt % 3;
        const uint2* As2 = (const uint2*)(smem + (size_t)s * STG) + (size_t)rA * RP2;
        const uint2* Bs2 = (const uint2*)(smem + (size_t)s * STG + TILE_A) + (size_t)rB * RP2;

#pragma unroll
        for (int ks = 0; ks < 4; ++ks) {
            int co = ks * 4 + qt;               // 8B slot within row
            uint2 a0[4], a1[4], bb[8];
#pragma unroll
            for (int mi = 0; mi < 4; ++mi) {
                a0[mi] = As2[(mi * 16)     * RP2 + co];
                a1[mi] = As2[(mi * 16 + 8) * RP2 + co];
            }
#pragma unroll
            for (int ni = 0; ni < 8; ++ni)
                bb[ni] = Bs2[(ni * 8) * RP2 + co];
#pragma unroll
            for (int mi = 0; mi < 4; ++mi)
#pragma unroll
                for (int ni = 0; ni < 8; ++ni)
                    mma8(acc[mi][ni], a0[mi].x, a1[mi].x, a0[mi].y, a1[mi].y,
                         bb[ni].x, bb[ni].y);
        }
        if (jt + 2 < NKT) load_tile(sb, tid, m0, n0, jt + 2, (jt + 2) % 3);
    }

#pragma unroll
    for (int mi = 0; mi < 4; ++mi) {
        int r0 = m0 + wm * 64 + mi * 16 + qr;
#pragma unroll
        for (int ni = 0; ni < 8; ++ni) {
            int n = n0 + wn * 64 + ni * 8 + 2 * qt;
            float b0 = bias[n], b1 = bias[n + 1];
            float2 v0 = {acc[mi][ni][0] + b0, acc[mi][ni][1] + b1};
            float2 v1 = {acc[mi][ni][2] + b0, acc[mi][ni][3] + b1};
            *reinterpret_cast<float2*>(out + (size_t)r0 * Ndim + n) = v0;
            *reinterpret_cast<float2*>(out + (size_t)(r0 + 8) * Ndim + n) = v1;
        }
    }
}

extern "C" void kernel_launch(void* const* d_in, const int* in_sizes, int n_in,
                              void* d_out, int out_size) {
    const float* inp  = (const float*)d_in[0];
    const int*   qw   = (const int*)d_in[1];
    const float* sc   = (const float*)d_in[2];
    const float* bias = (const float*)d_in[3];
    float* out = (float*)d_out;

    cudaFuncSetAttribute(gemm_k, cudaFuncAttributeMaxDynamicSharedMemorySize, SMEM_BYTES);

    dequant_k<<<dim3(Ndim / 32, Kdim / 32), dim3(32, 8)>>>(qw, sc);
    round_a_k<<<(int)((size_t)Mdim * Kdim / 2 / 256), 256>>>(inp);
    gemm_k<<<dim3(Ndim / NT, Mdim / MT), 256, SMEM_BYTES>>>(bias, out);
}

// round 7
// speedup vs baseline: 2.2154x; 1.8318x over previous
#include <cuda_runtime.h>
#include <cuda_fp16.h>
#include <cstdint>
#include <cstddef>

#define DI __device__ __forceinline__

static constexpr int Mdim = 8192, Ndim = 4096, Kdim = 4096;
static constexpr int MT = 256, NT = 128, KT = 64;
static constexpr int NKT = Kdim / KT;              // 64
static constexpr int ROWB = 160;                   // row stride in bytes (128B data + pad)
static constexpr int RP8 = ROWB / 8;               // row stride in 8B units (20)
static constexpr int TILE_A = 256 * ROWB;          // 40960 B
static constexpr int TILE_B = 128 * ROWB;          // 20480 B
static constexpr int STG = TILE_A + TILE_B;        // 61440 B
static constexpr unsigned SMEM_BYTES = 3 * STG;    // 184320

// fp16, k-interleaved within each 16-k group: word slots [k0k1 k8k9 k2k3 k10k11 k4k5 k12k13 k6k7 k14k15]
__device__ __half g_wt[(size_t)Ndim * Kdim];       // W^T [n][k]
__device__ __half g_a [(size_t)Mdim * Kdim];       // A   [m][k]

DI uint32_t smem_u32(const void* p) {
    uint32_t a;
    asm("{ .reg .u64 t; cvta.to.shared.u64 t, %1; cvt.u32.u64 %0, t; }" : "=r"(a) : "l"(p));
    return a;
}
DI void cpa16(uint32_t dst, const void* src) {
    asm volatile("cp.async.cg.shared.global [%0], [%1], 16;" :: "r"(dst), "l"(src) : "memory");
}
DI void cpa_commit() { asm volatile("cp.async.commit_group;" ::: "memory"); }
template <int N> DI void cpa_wait() {
    asm volatile("cp.async.wait_group %0;" :: "n"(N) : "memory");
}
DI void mma16(float* d, uint32_t a0, uint32_t a1, uint32_t a2, uint32_t a3,
              uint32_t b0, uint32_t b1) {
    asm volatile(
        "mma.sync.aligned.m16n8k16.row.col.f32.f16.f16.f32 "
        "{%0,%1,%2,%3}, {%4,%5,%6,%7}, {%8,%9}, {%0,%1,%2,%3};"
        : "+f"(d[0]), "+f"(d[1]), "+f"(d[2]), "+f"(d[3])
        : "r"(a0), "r"(a1), "r"(a2), "r"(a3), "r"(b0), "r"(b1));
}

// interleaved position of k-index e within its 16-group
DI int ileave16(int e) {
    int p = (e >> 1) & 7, o = e & 1;
    int slot = ((p & 3) << 1) | (p >> 2);
    return (e & ~15) | (slot << 1) | o;
}

// ---------- prep 1: g_wt[n][ik] = fp16(q[k][n]*s[k][n/32]), transposed + interleaved ----------
__global__ void dequant_k(const int* __restrict__ q, const float* __restrict__ s) {
    __shared__ float t[32][33];
    int n0 = blockIdx.x * 32, k0 = blockIdx.y * 32;
    int tx = threadIdx.x, ty = threadIdx.y;   // 32 x 8
    int sb = n0 >> 5;
#pragma unroll
    for (int i = 0; i < 4; i++) {
        int k = k0 + ty + i * 8;
        t[ty + i * 8][tx] = (float)q[(size_t)k * Ndim + n0 + tx] * s[(size_t)k * (Ndim / 32) + sb];
    }
    __syncthreads();
    int itx = ileave16(tx);
#pragma unroll
    for (int i = 0; i < 4; i++)
        g_wt[(size_t)(n0 + ty + i * 8) * Kdim + k0 + itx] = __float2half_rn(t[tx][ty + i * 8]);
}

// ---------- prep 2: A f32 -> fp16 + interleave (one 16-k group per thread) ----------
__global__ void round_a_k(const float* __restrict__ in) {
    size_t idx = (size_t)blockIdx.x * blockDim.x + threadIdx.x;  // M*K/16
    size_t m = idx >> 8;                   // K/16 = 256 groups per row
    int g = (int)(idx & 255);
    const float* p = in + m * Kdim + g * 16;
    uint32_t w[8];
#pragma unroll
    for (int s = 0; s < 8; s++) {
        int pp = (s >> 1) + ((s & 1) << 2);       // pair index
        __half2 h = __floats2half2_rn(p[2 * pp], p[2 * pp + 1]);
        w[s] = *reinterpret_cast<uint32_t*>(&h);
    }
    uint4* dst = reinterpret_cast<uint4*>(g_a + m * Kdim + g * 16);
    dst[0] = make_uint4(w[0], w[1], w[2], w[3]);
    dst[1] = make_uint4(w[4], w[5], w[6], w[7]);
}

// ---------- GEMM: fp16 mma.sync m16n8k16, 256x128x64 CTA, 256 thr, warp 64x64 ----------
DI void load_tile(uint32_t sb, int tid, int m0, int n0, int jt, int s) {
    const __half* Ap = g_a  + (size_t)m0 * Kdim + jt * KT;
    const __half* Bp = g_wt + (size_t)n0 * Kdim + jt * KT;
    uint32_t base = sb + (uint32_t)s * STG;
#pragma unroll
    for (int i = 0; i < 12; i++) {
        int idx = tid + i * 256;                 // 0..3071
        if (idx < 2048) {                        // A: 256 rows x 8 chunks of 16B
            int r = idx >> 3, c = idx & 7;
            cpa16(base + (uint32_t)(r * ROWB + c * 16), Ap + (size_t)r * Kdim + c * 8);
        } else {                                 // B: 128 rows x 8 chunks
            int j = idx - 2048;
            int r = j >> 3, c = j & 7;
            cpa16(base + TILE_A + (uint32_t)(r * ROWB + c * 16), Bp + (size_t)r * Kdim + c * 8);
        }
    }
    cpa_commit();
}

__global__ void __launch_bounds__(256, 1) gemm_k(const float* __restrict__ bias,
                                                 float* __restrict__ out) {
    extern __shared__ __align__(1024) char smem[];
    uint32_t sb = smem_u32(smem);
    int tid = threadIdx.x, wid = tid >> 5, lane = tid & 31;
    int qr = lane >> 2, qt = lane & 3;
    int wm = wid >> 1, wn = wid & 1;            // 4 x 2 warp grid, 64x64 warp tile
    int n0 = blockIdx.x * NT, m0 = blockIdx.y * MT;
    int rA = wm * 64 + qr;
    int rB = wn * 64 + qr;

    float acc[4][8][4];
#pragma unroll
    for (int a = 0; a < 4; a++)
#pragma unroll
        for (int b = 0; b < 8; b++)
#pragma unroll
            for (int c = 0; c < 4; c++) acc[a][b][c] = 0.f;

    load_tile(sb, tid, m0, n0, 0, 0);
    load_tile(sb, tid, m0, n0, 1, 1);

    for (int jt = 0; jt < NKT; ++jt) {
        if (jt + 1 < NKT) cpa_wait<1>(); else cpa_wait<0>();
        __syncthreads();

        int s = jt % 3;
        const uint2* As2 = (const uint2*)(smem + (size_t)s * STG) + (size_t)rA * RP8;
        const uint2* Bs2 = (const uint2*)(smem + (size_t)s * STG + TILE_A) + (size_t)rB * RP8;

#pragma unroll
        for (int ks = 0; ks < 4; ++ks) {          // 4 x k16 steps
            int co = ks * 4 + qt;                 // 8B slot within row
            uint2 a02[4], a13[4], bb[8];
#pragma unroll
            for (int mi = 0; mi < 4; ++mi) {
                a02[mi] = As2[(mi * 16)     * RP8 + co];   // (a0, a2)
                a13[mi] = As2[(mi * 16 + 8) * RP8 + co];   // (a1, a3)
            }
#pragma unroll
            for (int ni = 0; ni < 8; ++ni)
                bb[ni] = Bs2[(ni * 8) * RP8 + co];         // (b0, b1)
#pragma unroll
            for (int mi = 0; mi < 4; ++mi)
#pragma unroll
                for (int ni = 0; ni < 8; ++ni)
                    mma16(acc[mi][ni], a02[mi].x, a13[mi].x, a02[mi].y, a13[mi].y,
                          bb[ni].x, bb[ni].y);
        }
        if (jt + 2 < NKT) load_tile(sb, tid, m0, n0, jt + 2, (jt + 2) % 3);
    }

#pragma unroll
    for (int mi = 0; mi < 4; ++mi) {
        int r0 = m0 + wm * 64 + mi * 16 + qr;
#pragma unroll
        for (int ni = 0; ni < 8; ++ni) {
            int n = n0 + wn * 64 + ni * 8 + 2 * qt;
            float b0 = bias[n], b1 = bias[n + 1];
            float2 v0 = {acc[mi][ni][0] + b0, acc[mi][ni][1] + b1};
            float2 v1 = {acc[mi][ni][2] + b0, acc[mi][ni][3] + b1};
            *reinterpret_cast<float2*>(out + (size_t)r0 * Ndim + n) = v0;
            *reinterpret_cast<float2*>(out + (size_t)(r0 + 8) * Ndim + n) = v1;
        }
    }
}

extern "C" void kernel_launch(void* const* d_in, const int* in_sizes, int n_in,
                              void* d_out, int out_size) {
    const float* inp  = (const float*)d_in[0];
    const int*   qw   = (const int*)d_in[1];
    const float* sc   = (const float*)d_in[2];
    const float* bias = (const float*)d_in[3];
    float* out = (float*)d_out;

    cudaFuncSetAttribute(gemm_k, cudaFuncAttributeMaxDynamicSharedMemorySize, SMEM_BYTES);

    dequant_k<<<dim3(Ndim / 32, Kdim / 32), dim3(32, 8)>>>(qw, sc);
    round_a_k<<<(int)((size_t)Mdim * Kdim / 16 / 256), 256>>>(inp);
    gemm_k<<<dim3(Ndim / NT, Mdim / MT), 256, SMEM_BYTES>>>(bias, out);
}